// round 2
// baseline (speedup 1.0000x reference)
#include <cuda_runtime.h>
#include <math.h>

#define Nn 20000
#define Ee 320000
#define Dd 256
#define Hh 8
#define DHd 32
#define FFd 1024
#define EDd 64

// ---------------- scratch (device globals; no allocation allowed) ----------
__device__ float g_xn [Nn*Dd];
__device__ float g_q  [Nn*Dd];
__device__ float g_k  [Nn*Dd];
__device__ float g_v  [Nn*Dd];
__device__ float g_ep [Ee*DHd];
__device__ float g_sc [Ee*Hh];
__device__ float g_m  [Nn*Hh];
__device__ float g_s  [Nn*Hh];
__device__ float g_agg[Nn*Dd];
__device__ float g_x1 [Nn*Dd];
__device__ float g_xn2[Nn*Dd];
__device__ float g_ff [Nn*FFd];

// ---------------- init: m=-inf, s=0, agg=0 ---------------------------------
__global__ void init_kernel()
{
    int i = blockIdx.x * blockDim.x + threadIdx.x;
    if (i < Nn * Hh) { g_m[i] = -INFINITY; g_s[i] = 0.0f; }
    if (i < Nn * Dd) g_agg[i] = 0.0f;
}

// ---------------- layernorm: one warp per row (D=256) ----------------------
__global__ void ln_kernel(const float* __restrict__ in, const float* __restrict__ g,
                          const float* __restrict__ b, float* __restrict__ out, int n)
{
    int warp = (blockIdx.x * blockDim.x + threadIdx.x) >> 5;
    int lane = threadIdx.x & 31;
    if (warp >= n) return;
    const float* row = in + (size_t)warp * Dd;
    float4 a0 = *(const float4*)(row + lane * 4);
    float4 a1 = *(const float4*)(row + 128 + lane * 4);
    float s = a0.x + a0.y + a0.z + a0.w + a1.x + a1.y + a1.z + a1.w;
    float q = a0.x*a0.x + a0.y*a0.y + a0.z*a0.z + a0.w*a0.w
            + a1.x*a1.x + a1.y*a1.y + a1.z*a1.z + a1.w*a1.w;
    #pragma unroll
    for (int off = 16; off >= 1; off >>= 1) {
        s += __shfl_xor_sync(0xffffffffu, s, off);
        q += __shfl_xor_sync(0xffffffffu, q, off);
    }
    float mean = s * (1.0f / 256.0f);
    float var  = q * (1.0f / 256.0f) - mean * mean;
    float inv  = rsqrtf(var + 1e-5f);
    float* orow = out + (size_t)warp * Dd;
    int c0 = lane * 4, c1 = 128 + lane * 4;
    float4 g0 = *(const float4*)(g + c0), g1 = *(const float4*)(g + c1);
    float4 b0 = *(const float4*)(b + c0), b1 = *(const float4*)(b + c1);
    float4 o0, o1;
    o0.x = (a0.x - mean) * inv * g0.x + b0.x;
    o0.y = (a0.y - mean) * inv * g0.y + b0.y;
    o0.z = (a0.z - mean) * inv * g0.z + b0.z;
    o0.w = (a0.w - mean) * inv * g0.w + b0.w;
    o1.x = (a1.x - mean) * inv * g1.x + b1.x;
    o1.y = (a1.y - mean) * inv * g1.y + b1.y;
    o1.z = (a1.z - mean) * inv * g1.z + b1.z;
    o1.w = (a1.w - mean) * inv * g1.w + b1.w;
    *(float4*)(orow + c0) = o0;
    *(float4*)(orow + c1) = o1;
}

// ---------------- tiled fp32 GEMM: C = A[M,K] @ B[K,Nc] + bias, epilogues --
// EPI 0: C = acc+bias
// EPI 1: C = gelu(acc+bias)          (exact erf gelu)
// EPI 2: C = res + scl[0]*(acc+bias)
#define BM 64
#define BN 64
#define BK 16

template<int EPI>
__global__ void gemm_kernel(const float* __restrict__ A, const float* __restrict__ B,
                            const float* __restrict__ bias, const float* __restrict__ res,
                            const float* __restrict__ scl, float* __restrict__ C,
                            int M, int Nc, int K)
{
    __shared__ float As[BK][BM];
    __shared__ float Bs[BK][BN];

    int tid = threadIdx.x;                 // 256 threads
    int innerRowA = tid >> 2;              // 0..63
    int innerColA = tid & 3;               // 0..3   (x4 floats)
    int innerRowB = tid >> 4;              // 0..15
    int innerColB = tid & 15;              // 0..15  (x4 floats)
    int threadRow = tid >> 4;              // 0..15
    int threadCol = tid & 15;              // 0..15

    int rowBase = blockIdx.x * BM;
    int colBase = blockIdx.y * BN;

    float acc[4][4];
    #pragma unroll
    for (int i = 0; i < 4; i++)
        #pragma unroll
        for (int j = 0; j < 4; j++) acc[i][j] = 0.0f;

    for (int k0 = 0; k0 < K; k0 += BK) {
        int r = rowBase + innerRowA;
        float4 a;
        if (r < M) a = *(const float4*)&A[(size_t)r * K + k0 + innerColA * 4];
        else       a = make_float4(0.f, 0.f, 0.f, 0.f);
        As[innerColA * 4 + 0][innerRowA] = a.x;
        As[innerColA * 4 + 1][innerRowA] = a.y;
        As[innerColA * 4 + 2][innerRowA] = a.z;
        As[innerColA * 4 + 3][innerRowA] = a.w;

        int kr = k0 + innerRowB;
        *(float4*)&Bs[innerRowB][innerColB * 4] =
            *(const float4*)&B[(size_t)kr * Nc + colBase + innerColB * 4];

        __syncthreads();

        #pragma unroll
        for (int kk = 0; kk < BK; kk++) {
            float4 ra = *(const float4*)&As[kk][threadRow * 4];
            float4 rb = *(const float4*)&Bs[kk][threadCol * 4];
            acc[0][0] += ra.x * rb.x; acc[0][1] += ra.x * rb.y;
            acc[0][2] += ra.x * rb.z; acc[0][3] += ra.x * rb.w;
            acc[1][0] += ra.y * rb.x; acc[1][1] += ra.y * rb.y;
            acc[1][2] += ra.y * rb.z; acc[1][3] += ra.y * rb.w;
            acc[2][0] += ra.z * rb.x; acc[2][1] += ra.z * rb.y;
            acc[2][2] += ra.z * rb.z; acc[2][3] += ra.z * rb.w;
            acc[3][0] += ra.w * rb.x; acc[3][1] += ra.w * rb.y;
            acc[3][2] += ra.w * rb.z; acc[3][3] += ra.w * rb.w;
        }
        __syncthreads();
    }

    float sv = (EPI == 2) ? scl[0] : 0.0f;
    #pragma unroll
    for (int i = 0; i < 4; i++) {
        int r = rowBase + threadRow * 4 + i;
        if (r >= M) continue;
        #pragma unroll
        for (int j = 0; j < 4; j++) {
            int c = colBase + threadCol * 4 + j;
            float val = acc[i][j] + bias[c];
            size_t idx = (size_t)r * Nc + c;
            if (EPI == 1) {
                val = 0.5f * val * (1.0f + erff(val * 0.70710678118654752f));
            } else if (EPI == 2) {
                val = res[idx] + sv * val;
            }
            C[idx] = val;
        }
    }
}

// ---------------- edge projection: ep = ef[E,64] @ We[64,32] + be ----------
__global__ void ep_kernel(const float* __restrict__ ef, const float* __restrict__ We,
                          const float* __restrict__ be)
{
    __shared__ float sW[EDd * DHd];   // 2048 floats
    __shared__ float sE[8 * EDd];     // 8 edges x 64
    int tid = threadIdx.x;            // 256
    #pragma unroll
    for (int i = 0; i < 8; i++) sW[tid + i * 256] = We[tid + i * 256];
    float bj = be[tid & 31];
    __syncthreads();

    int j  = tid & 31;
    int ty = tid >> 5;                // local edge 0..7

    for (int e0 = blockIdx.x * 8; e0 < Ee; e0 += gridDim.x * 8) {
        sE[tid]       = ef[(size_t)e0 * EDd + tid];
        sE[tid + 256] = ef[(size_t)e0 * EDd + tid + 256];
        __syncthreads();
        float acc = 0.0f;
        #pragma unroll
        for (int k = 0; k < EDd; k++)
            acc += sE[ty * EDd + k] * sW[k * DHd + j];
        g_ep[(size_t)(e0 + ty) * DHd + j] = acc + bj;
        __syncthreads();
    }
}

__device__ __forceinline__ void atomicMaxFloat(float* addr, float value)
{
    if (value >= 0.0f) atomicMax((int*)addr, __float_as_int(value));
    else               atomicMin((unsigned int*)addr, __float_as_uint(value));
}

// ---------------- scores: one warp per edge --------------------------------
__global__ void score_kernel(const int* __restrict__ eidx, const float* __restrict__ ew)
{
    int e = (blockIdx.x * blockDim.x + threadIdx.x) >> 5;
    int lane = threadIdx.x & 31;
    if (e >= Ee) return;
    int src = eidx[e];
    int dst = eidx[Ee + e];
    float epd = g_ep[(size_t)e * DHd + lane];
    float w = ew[e] * 0.17677669529663687f;     // * DH^-0.5
    const float* qrow = g_q + (size_t)dst * Dd;
    const float* krow = g_k + (size_t)src * Dd;
    #pragma unroll
    for (int h = 0; h < Hh; h++) {
        float p = qrow[h * DHd + lane] * (krow[h * DHd + lane] + epd);
        #pragma unroll
        for (int off = 16; off >= 1; off >>= 1)
            p += __shfl_xor_sync(0xffffffffu, p, off);
        if (lane == 0) {
            float sc = p * w;
            g_sc[(size_t)e * Hh + h] = sc;
            atomicMaxFloat(&g_m[dst * Hh + h], sc);
        }
    }
}

// ---------------- exp + segment sum ----------------------------------------
__global__ void ex_kernel(const int* __restrict__ eidx)
{
    int i = blockIdx.x * blockDim.x + threadIdx.x;
    if (i >= Ee * Hh) return;
    int e = i >> 3, h = i & 7;
    int dst = eidx[Ee + e];
    float v = expf(g_sc[i] - g_m[dst * Hh + h]);
    g_sc[i] = v;
    atomicAdd(&g_s[dst * Hh + h], v);
}

// ---------------- weighted V aggregation: one warp per edge ----------------
__global__ void agg_kernel(const int* __restrict__ eidx)
{
    int e = (blockIdx.x * blockDim.x + threadIdx.x) >> 5;
    int lane = threadIdx.x & 31;
    if (e >= Ee) return;
    int src = eidx[e];
    int dst = eidx[Ee + e];
    float aval = 0.0f;
    if (lane < 8)
        aval = g_sc[(size_t)e * Hh + lane] / g_s[dst * Hh + lane];
    const float* vrow = g_v + (size_t)src * Dd;
    float* orow = g_agg + (size_t)dst * Dd;
    #pragma unroll
    for (int h = 0; h < Hh; h++) {
        float a = __shfl_sync(0xffffffffu, aval, h);
        float vd = vrow[h * DHd + lane];
        atomicAdd(&orow[h * DHd + lane], a * vd);
    }
}

// ---------------- launch ----------------------------------------------------
extern "C" void kernel_launch(void* const* d_in, const int* in_sizes, int n_in,
                              void* d_out, int out_size)
{
    const float* x    = (const float*)d_in[0];
    const float* ef   = (const float*)d_in[1];
    const float* ew   = (const float*)d_in[2];
    const int*   eidx = (const int*)  d_in[3];
    const float* Wq   = (const float*)d_in[4];
    const float* bq   = (const float*)d_in[5];
    const float* Wk   = (const float*)d_in[6];
    const float* bk   = (const float*)d_in[7];
    const float* Wv   = (const float*)d_in[8];
    const float* bv   = (const float*)d_in[9];
    const float* We   = (const float*)d_in[10];
    const float* be   = (const float*)d_in[11];
    const float* Wo   = (const float*)d_in[12];
    const float* bo   = (const float*)d_in[13];
    const float* ln1g = (const float*)d_in[14];
    const float* ln1b = (const float*)d_in[15];
    const float* ln2g = (const float*)d_in[16];
    const float* ln2b = (const float*)d_in[17];
    const float* W1   = (const float*)d_in[18];
    const float* b1   = (const float*)d_in[19];
    const float* W2   = (const float*)d_in[20];
    const float* b2   = (const float*)d_in[21];
    const float* alpha= (const float*)d_in[22];
    const float* beta = (const float*)d_in[23];
    float* out = (float*)d_out;

    // Resolve scratch addresses every call (host-side queries; capture-safe,
    // no static guards / caching).
    float *p_xn, *p_q, *p_k, *p_v, *p_agg, *p_x1, *p_xn2, *p_ff;
    cudaGetSymbolAddress((void**)&p_xn,  g_xn);
    cudaGetSymbolAddress((void**)&p_q,   g_q);
    cudaGetSymbolAddress((void**)&p_k,   g_k);
    cudaGetSymbolAddress((void**)&p_v,   g_v);
    cudaGetSymbolAddress((void**)&p_agg, g_agg);
    cudaGetSymbolAddress((void**)&p_x1,  g_x1);
    cudaGetSymbolAddress((void**)&p_xn2, g_xn2);
    cudaGetSymbolAddress((void**)&p_ff,  g_ff);

    dim3 blk(256);

    // 0. init segment-softmax state
    init_kernel<<<(Nn * Dd + 255) / 256, blk>>>();

    // 1. ln1
    ln_kernel<<<(Nn + 7) / 8, blk>>>(x, ln1g, ln1b, p_xn, Nn);

    // 2. QKV
    dim3 gqkv((Nn + BM - 1) / BM, Dd / BN);
    gemm_kernel<0><<<gqkv, blk>>>(p_xn, Wq, bq, nullptr, nullptr, p_q, Nn, Dd, Dd);
    gemm_kernel<0><<<gqkv, blk>>>(p_xn, Wk, bk, nullptr, nullptr, p_k, Nn, Dd, Dd);
    gemm_kernel<0><<<gqkv, blk>>>(p_xn, Wv, bv, nullptr, nullptr, p_v, Nn, Dd, Dd);

    // 3. edge projection
    ep_kernel<<<4096, blk>>>(ef, We, be);

    // 4-6. edge attention
    score_kernel<<<(Ee + 7) / 8, blk>>>(eidx, ew);
    ex_kernel<<<(Ee * Hh + 255) / 256, blk>>>(eidx);
    agg_kernel<<<(Ee + 7) / 8, blk>>>(eidx);

    // 7. Wo projection + residual (x1 = x + alpha*(agg@Wo+bo))
    gemm_kernel<2><<<gqkv, blk>>>(p_agg, Wo, bo, x, alpha, p_x1, Nn, Dd, Dd);

    // 8. ln2
    ln_kernel<<<(Nn + 7) / 8, blk>>>(p_x1, ln2g, ln2b, p_xn2, Nn);

    // 9. FF up + gelu
    dim3 gff1((Nn + BM - 1) / BM, FFd / BN);
    gemm_kernel<1><<<gff1, blk>>>(p_xn2, W1, b1, nullptr, nullptr, p_ff, Nn, FFd, Dd);

    // 10. FF down + residual -> out
    gemm_kernel<2><<<gqkv, blk>>>(p_ff, W2, b2, p_x1, beta, out, Nn, Dd, FFd);
}

// round 3
// speedup vs baseline: 1.5585x; 1.5585x over previous
#include <cuda_runtime.h>
#include <math.h>
#include <stdint.h>

#define Nn 20000
#define Ee 320000
#define Dd 256
#define Hh 8
#define DHd 32
#define FFd 1024
#define EDd 64

// ---------------- scratch (device globals; no allocation allowed) ----------
__device__ float g_xn [Nn*Dd];
__device__ float g_q  [Nn*Dd];
__device__ float g_k  [Nn*Dd];
__device__ float g_v  [Nn*Dd];
__device__ float g_ep [Ee*DHd];
__device__ float g_sc [Ee*Hh];
__device__ float g_m  [Nn*Hh];
__device__ float g_s  [Nn*Hh];
__device__ float g_agg[Nn*Dd];
__device__ float g_x1 [Nn*Dd];
__device__ float g_xn2[Nn*Dd];
__device__ float g_ff [Nn*FFd];

// ---------------- init: m=-inf, s=0, agg=0 ---------------------------------
__global__ void init_kernel()
{
    int i = blockIdx.x * blockDim.x + threadIdx.x;
    if (i < Nn * Hh) { g_m[i] = -INFINITY; g_s[i] = 0.0f; }
    if (i < Nn * Dd) g_agg[i] = 0.0f;
}

// ---------------- layernorm: one warp per row (D=256) ----------------------
__global__ void ln_kernel(const float* __restrict__ in, const float* __restrict__ g,
                          const float* __restrict__ b, float* __restrict__ out, int n)
{
    int warp = (blockIdx.x * blockDim.x + threadIdx.x) >> 5;
    int lane = threadIdx.x & 31;
    if (warp >= n) return;
    const float* row = in + (size_t)warp * Dd;
    float4 a0 = *(const float4*)(row + lane * 4);
    float4 a1 = *(const float4*)(row + 128 + lane * 4);
    float s = a0.x + a0.y + a0.z + a0.w + a1.x + a1.y + a1.z + a1.w;
    float q = a0.x*a0.x + a0.y*a0.y + a0.z*a0.z + a0.w*a0.w
            + a1.x*a1.x + a1.y*a1.y + a1.z*a1.z + a1.w*a1.w;
    #pragma unroll
    for (int off = 16; off >= 1; off >>= 1) {
        s += __shfl_xor_sync(0xffffffffu, s, off);
        q += __shfl_xor_sync(0xffffffffu, q, off);
    }
    float mean = s * (1.0f / 256.0f);
    float var  = q * (1.0f / 256.0f) - mean * mean;
    float inv  = rsqrtf(var + 1e-5f);
    float* orow = out + (size_t)warp * Dd;
    int c0 = lane * 4, c1 = 128 + lane * 4;
    float4 g0 = *(const float4*)(g + c0), g1 = *(const float4*)(g + c1);
    float4 b0 = *(const float4*)(b + c0), b1 = *(const float4*)(b + c1);
    float4 o0, o1;
    o0.x = (a0.x - mean) * inv * g0.x + b0.x;
    o0.y = (a0.y - mean) * inv * g0.y + b0.y;
    o0.z = (a0.z - mean) * inv * g0.z + b0.z;
    o0.w = (a0.w - mean) * inv * g0.w + b0.w;
    o1.x = (a1.x - mean) * inv * g1.x + b1.x;
    o1.y = (a1.y - mean) * inv * g1.y + b1.y;
    o1.z = (a1.z - mean) * inv * g1.z + b1.z;
    o1.w = (a1.w - mean) * inv * g1.w + b1.w;
    *(float4*)(orow + c0) = o0;
    *(float4*)(orow + c1) = o1;
}

// ---------------- tf32 tensor-core GEMM ------------------------------------
// C[M,Nc] = epilogue(A[M,K] @ B[K,Nc] + bias)
// EPI 0: C = acc+bias
// EPI 1: C = gelu(acc+bias)          (exact erf gelu)
// EPI 2: C = res + scl[0]*(acc+bias)
// Block tile 128x128, BK=16, 8 warps (2 x 4), warp tile 64x32,
// mma.m16n8k8.tf32.  Smem stride 136 words -> conflict-free fragment LDS.

#define TBM 128
#define TBN 128
#define TBK 16
#define SSTR 136

__device__ __forceinline__ uint32_t f2tf32(float f)
{
    uint32_t r;
    asm("cvt.rna.tf32.f32 %0, %1;" : "=r"(r) : "f"(f));
    return r;
}

__device__ __forceinline__ void mma_tf32(float d[4], const uint32_t a[4],
                                         const uint32_t b[2], const float c[4])
{
    asm volatile(
        "mma.sync.aligned.m16n8k8.row.col.f32.tf32.tf32.f32 "
        "{%0,%1,%2,%3}, {%4,%5,%6,%7}, {%8,%9}, {%10,%11,%12,%13};\n"
        : "=f"(d[0]), "=f"(d[1]), "=f"(d[2]), "=f"(d[3])
        : "r"(a[0]), "r"(a[1]), "r"(a[2]), "r"(a[3]),
          "r"(b[0]), "r"(b[1]),
          "f"(c[0]), "f"(c[1]), "f"(c[2]), "f"(c[3]));
}

template<int EPI>
__global__ __launch_bounds__(256)
void mma_gemm_kernel(const float* __restrict__ A, const float* __restrict__ B,
                     const float* __restrict__ bias, const float* __restrict__ res,
                     const float* __restrict__ scl, float* __restrict__ C,
                     int M, int Nc, int K)
{
    __shared__ uint32_t As[TBK * SSTR];   // [k][m]
    __shared__ uint32_t Bs[TBK * SSTR];   // [k][n]

    int tid  = threadIdx.x;
    int lane = tid & 31;
    int warp = tid >> 5;
    int warpM = warp & 1;        // 0..1  (64 rows each)
    int warpN = warp >> 1;       // 0..3  (32 cols each)
    int g  = lane >> 2;          // groupID 0..7
    int tg = lane & 3;           // thread-in-group 0..3

    int rowBase = blockIdx.x * TBM;
    int colBase = blockIdx.y * TBN;

    float acc[4][4][4];
    #pragma unroll
    for (int i = 0; i < 4; i++)
        #pragma unroll
        for (int j = 0; j < 4; j++)
            #pragma unroll
            for (int l = 0; l < 4; l++) acc[i][j][l] = 0.0f;

    for (int k0 = 0; k0 < K; k0 += TBK) {
        // ---- fill A tile (transposed to [k][m]), tf32 convert at store ----
        #pragma unroll
        for (int it = 0; it < 2; it++) {
            int t   = tid + it * 256;          // 0..511
            int row = t >> 2;                  // 0..127
            int kc  = (t & 3) * 4;             // 0,4,8,12
            int r   = rowBase + row;
            float4 v = make_float4(0.f, 0.f, 0.f, 0.f);
            if (r < M) v = *(const float4*)&A[(size_t)r * K + k0 + kc];
            As[(kc + 0) * SSTR + row] = f2tf32(v.x);
            As[(kc + 1) * SSTR + row] = f2tf32(v.y);
            As[(kc + 2) * SSTR + row] = f2tf32(v.z);
            As[(kc + 3) * SSTR + row] = f2tf32(v.w);
        }
        // ---- fill B tile [k][n] ----
        #pragma unroll
        for (int it = 0; it < 2; it++) {
            int t  = tid + it * 256;           // 0..511
            int k  = t >> 5;                   // 0..15
            int n4 = (t & 31) * 4;             // 0..124
            float4 v = *(const float4*)&B[(size_t)(k0 + k) * Nc + colBase + n4];
            uint4 u;
            u.x = f2tf32(v.x); u.y = f2tf32(v.y);
            u.z = f2tf32(v.z); u.w = f2tf32(v.w);
            *(uint4*)&Bs[k * SSTR + n4] = u;
        }
        __syncthreads();

        // ---- 2 k-steps of 8 ----
        #pragma unroll
        for (int ks = 0; ks < 2; ks++) {
            int kb = ks * 8;
            uint32_t af[4][4], bf[4][2];
            #pragma unroll
            for (int mt = 0; mt < 4; mt++) {
                int m = warpM * 64 + mt * 16;
                af[mt][0] = As[(kb + tg)     * SSTR + m + g];
                af[mt][1] = As[(kb + tg)     * SSTR + m + g + 8];
                af[mt][2] = As[(kb + tg + 4) * SSTR + m + g];
                af[mt][3] = As[(kb + tg + 4) * SSTR + m + g + 8];
            }
            #pragma unroll
            for (int nt = 0; nt < 4; nt++) {
                int n = warpN * 32 + nt * 8;
                bf[nt][0] = Bs[(kb + tg)     * SSTR + n + g];
                bf[nt][1] = Bs[(kb + tg + 4) * SSTR + n + g];
            }
            #pragma unroll
            for (int mt = 0; mt < 4; mt++)
                #pragma unroll
                for (int nt = 0; nt < 4; nt++)
                    mma_tf32(acc[mt][nt], af[mt], bf[nt], acc[mt][nt]);
        }
        __syncthreads();
    }

    // ---- epilogue ----
    float sv = (EPI == 2) ? scl[0] : 0.0f;
    #pragma unroll
    for (int mt = 0; mt < 4; mt++) {
        int r0 = rowBase + warpM * 64 + mt * 16 + g;
        int r1 = r0 + 8;
        #pragma unroll
        for (int nt = 0; nt < 4; nt++) {
            int cc = colBase + warpN * 32 + nt * 8 + tg * 2;
            float bb0 = bias[cc], bb1 = bias[cc + 1];
            if (r0 < M) {
                float v0 = acc[mt][nt][0] + bb0;
                float v1 = acc[mt][nt][1] + bb1;
                size_t i0 = (size_t)r0 * Nc + cc;
                if (EPI == 1) {
                    v0 = 0.5f * v0 * (1.0f + erff(v0 * 0.70710678118654752f));
                    v1 = 0.5f * v1 * (1.0f + erff(v1 * 0.70710678118654752f));
                } else if (EPI == 2) {
                    v0 = res[i0]     + sv * v0;
                    v1 = res[i0 + 1] + sv * v1;
                }
                C[i0] = v0; C[i0 + 1] = v1;
            }
            if (r1 < M) {
                float v2 = acc[mt][nt][2] + bb0;
                float v3 = acc[mt][nt][3] + bb1;
                size_t i1 = (size_t)r1 * Nc + cc;
                if (EPI == 1) {
                    v2 = 0.5f * v2 * (1.0f + erff(v2 * 0.70710678118654752f));
                    v3 = 0.5f * v3 * (1.0f + erff(v3 * 0.70710678118654752f));
                } else if (EPI == 2) {
                    v2 = res[i1]     + sv * v2;
                    v3 = res[i1 + 1] + sv * v3;
                }
                C[i1] = v2; C[i1 + 1] = v3;
            }
        }
    }
}

// ---------------- edge projection: ep = ef[E,64] @ We[64,32] + be ----------
__global__ void ep_kernel(const float* __restrict__ ef, const float* __restrict__ We,
                          const float* __restrict__ be)
{
    __shared__ float sW[EDd * DHd];   // 2048 floats
    __shared__ float sE[8 * EDd];     // 8 edges x 64
    int tid = threadIdx.x;            // 256
    #pragma unroll
    for (int i = 0; i < 8; i++) sW[tid + i * 256] = We[tid + i * 256];
    float bj = be[tid & 31];
    __syncthreads();

    int j  = tid & 31;
    int ty = tid >> 5;                // local edge 0..7

    for (int e0 = blockIdx.x * 8; e0 < Ee; e0 += gridDim.x * 8) {
        sE[tid]       = ef[(size_t)e0 * EDd + tid];
        sE[tid + 256] = ef[(size_t)e0 * EDd + tid + 256];
        __syncthreads();
        float acc = 0.0f;
        #pragma unroll
        for (int k = 0; k < EDd; k++)
            acc += sE[ty * EDd + k] * sW[k * DHd + j];
        g_ep[(size_t)(e0 + ty) * DHd + j] = acc + bj;
        __syncthreads();
    }
}

__device__ __forceinline__ void atomicMaxFloat(float* addr, float value)
{
    if (value >= 0.0f) atomicMax((int*)addr, __float_as_int(value));
    else               atomicMin((unsigned int*)addr, __float_as_uint(value));
}

// ---------------- scores: one warp per edge --------------------------------
__global__ void score_kernel(const int* __restrict__ eidx, const float* __restrict__ ew)
{
    int e = (blockIdx.x * blockDim.x + threadIdx.x) >> 5;
    int lane = threadIdx.x & 31;
    if (e >= Ee) return;
    int src = eidx[e];
    int dst = eidx[Ee + e];
    float epd = g_ep[(size_t)e * DHd + lane];
    float w = ew[e] * 0.17677669529663687f;     // * DH^-0.5
    const float* qrow = g_q + (size_t)dst * Dd;
    const float* krow = g_k + (size_t)src * Dd;
    #pragma unroll
    for (int h = 0; h < Hh; h++) {
        float p = qrow[h * DHd + lane] * (krow[h * DHd + lane] + epd);
        #pragma unroll
        for (int off = 16; off >= 1; off >>= 1)
            p += __shfl_xor_sync(0xffffffffu, p, off);
        if (lane == 0) {
            float sc = p * w;
            g_sc[(size_t)e * Hh + h] = sc;
            atomicMaxFloat(&g_m[dst * Hh + h], sc);
        }
    }
}

// ---------------- exp + segment sum ----------------------------------------
__global__ void ex_kernel(const int* __restrict__ eidx)
{
    int i = blockIdx.x * blockDim.x + threadIdx.x;
    if (i >= Ee * Hh) return;
    int e = i >> 3, h = i & 7;
    int dst = eidx[Ee + e];
    float v = expf(g_sc[i] - g_m[dst * Hh + h]);
    g_sc[i] = v;
    atomicAdd(&g_s[dst * Hh + h], v);
}

// ---------------- weighted V aggregation: one warp per edge ----------------
__global__ void agg_kernel(const int* __restrict__ eidx)
{
    int e = (blockIdx.x * blockDim.x + threadIdx.x) >> 5;
    int lane = threadIdx.x & 31;
    if (e >= Ee) return;
    int src = eidx[e];
    int dst = eidx[Ee + e];
    float aval = 0.0f;
    if (lane < 8)
        aval = g_sc[(size_t)e * Hh + lane] / g_s[dst * Hh + lane];
    const float* vrow = g_v + (size_t)src * Dd;
    float* orow = g_agg + (size_t)dst * Dd;
    #pragma unroll
    for (int h = 0; h < Hh; h++) {
        float a = __shfl_sync(0xffffffffu, aval, h);
        float vd = vrow[h * DHd + lane];
        atomicAdd(&orow[h * DHd + lane], a * vd);
    }
}

// ---------------- launch ----------------------------------------------------
extern "C" void kernel_launch(void* const* d_in, const int* in_sizes, int n_in,
                              void* d_out, int out_size)
{
    const float* x    = (const float*)d_in[0];
    const float* ef   = (const float*)d_in[1];
    const float* ew   = (const float*)d_in[2];
    const int*   eidx = (const int*)  d_in[3];
    const float* Wq   = (const float*)d_in[4];
    const float* bq   = (const float*)d_in[5];
    const float* Wk   = (const float*)d_in[6];
    const float* bk   = (const float*)d_in[7];
    const float* Wv   = (const float*)d_in[8];
    const float* bv   = (const float*)d_in[9];
    const float* We   = (const float*)d_in[10];
    const float* be   = (const float*)d_in[11];
    const float* Wo   = (const float*)d_in[12];
    const float* bo   = (const float*)d_in[13];
    const float* ln1g = (const float*)d_in[14];
    const float* ln1b = (const float*)d_in[15];
    const float* ln2g = (const float*)d_in[16];
    const float* ln2b = (const float*)d_in[17];
    const float* W1   = (const float*)d_in[18];
    const float* b1   = (const float*)d_in[19];
    const float* W2   = (const float*)d_in[20];
    const float* b2   = (const float*)d_in[21];
    const float* alpha= (const float*)d_in[22];
    const float* beta = (const float*)d_in[23];
    float* out = (float*)d_out;

    float *p_xn, *p_q, *p_k, *p_v, *p_agg, *p_x1, *p_xn2, *p_ff;
    cudaGetSymbolAddress((void**)&p_xn,  g_xn);
    cudaGetSymbolAddress((void**)&p_q,   g_q);
    cudaGetSymbolAddress((void**)&p_k,   g_k);
    cudaGetSymbolAddress((void**)&p_v,   g_v);
    cudaGetSymbolAddress((void**)&p_agg, g_agg);
    cudaGetSymbolAddress((void**)&p_x1,  g_x1);
    cudaGetSymbolAddress((void**)&p_xn2, g_xn2);
    cudaGetSymbolAddress((void**)&p_ff,  g_ff);

    dim3 blk(256);

    // 0. init segment-softmax state
    init_kernel<<<(Nn * Dd + 255) / 256, blk>>>();

    // 1. ln1
    ln_kernel<<<(Nn + 7) / 8, blk>>>(x, ln1g, ln1b, p_xn, Nn);

    // 2. QKV (tf32 tensor cores)
    dim3 gqkv((Nn + TBM - 1) / TBM, Dd / TBN);
    mma_gemm_kernel<0><<<gqkv, blk>>>(p_xn, Wq, bq, nullptr, nullptr, p_q, Nn, Dd, Dd);
    mma_gemm_kernel<0><<<gqkv, blk>>>(p_xn, Wk, bk, nullptr, nullptr, p_k, Nn, Dd, Dd);
    mma_gemm_kernel<0><<<gqkv, blk>>>(p_xn, Wv, bv, nullptr, nullptr, p_v, Nn, Dd, Dd);

    // 3. edge projection
    ep_kernel<<<4096, blk>>>(ef, We, be);

    // 4-6. edge attention
    score_kernel<<<(Ee + 7) / 8, blk>>>(eidx, ew);
    ex_kernel<<<(Ee * Hh + 255) / 256, blk>>>(eidx);
    agg_kernel<<<(Ee + 7) / 8, blk>>>(eidx);

    // 7. Wo projection + residual (x1 = x + alpha*(agg@Wo+bo))
    mma_gemm_kernel<2><<<gqkv, blk>>>(p_agg, Wo, bo, x, alpha, p_x1, Nn, Dd, Dd);

    // 8. ln2
    ln_kernel<<<(Nn + 7) / 8, blk>>>(p_x1, ln2g, ln2b, p_xn2, Nn);

    // 9. FF up + gelu
    dim3 gff1((Nn + TBM - 1) / TBM, FFd / TBN);
    mma_gemm_kernel<1><<<gff1, blk>>>(p_xn2, W1, b1, nullptr, nullptr, p_ff, Nn, FFd, Dd);

    // 10. FF down + residual -> out
    mma_gemm_kernel<2><<<gqkv, blk>>>(p_ff, W2, b2, p_x1, beta, out, Nn, Dd, FFd);
}